// round 12
// baseline (speedup 1.0000x reference)
#include <cuda_runtime.h>
#include <cuda_fp16.h>
#include <math.h>
#include <stdint.h>

#define N_NODES   51200
#define NUM_AUD   64
#define NODES_PER 800
#define E_EDGES   409600
#define NEG       0.2f
#define BCAP      64

// ---------------- scratch ----------------------------------------------------
__device__ __half g_h16[(size_t)N_NODES * 512];
__device__ __half g_mh[(size_t)N_NODES * 256];
__device__ __half g_emb16[(size_t)N_NODES * 256];
__device__ __half g_x16[(size_t)N_NODES * 512];
__device__ __half g_w1t[512 * 512];
__device__ __half g_w2t[512 * 256];
__device__ float  g_al[(size_t)N_NODES * 4];   // als = [0,2N), ald = [2N,4N)
__device__ float2 g_alpha[(size_t)N_NODES * BCAP];
__device__ int    g_deg[N_NODES];
__device__ int    g_bucket[(size_t)N_NODES * BCAP];

// ---------------- PTX helpers --------------------------------------------------
__device__ __forceinline__ uint32_t smem_u32(const void* p) {
    uint32_t a;
    asm("{ .reg .u64 t; cvta.to.shared.u64 t, %1; cvt.u32.u64 %0, t; }" : "=r"(a) : "l"(p));
    return a;
}
#define CP_ASYNC16(sa, ga) asm volatile("cp.async.cg.shared.global [%0], [%1], 16;" :: "r"(sa), "l"(ga))
#define CP_COMMIT()        asm volatile("cp.async.commit_group;" ::: "memory")
#define CP_WAIT(n)         asm volatile("cp.async.wait_group %0;" :: "n"(n) : "memory")

#define LDMATRIX_X4(r0, r1, r2, r3, ad) \
    asm volatile("ldmatrix.sync.aligned.m8n8.x4.shared.b16 {%0,%1,%2,%3}, [%4];" \
        : "=r"(r0), "=r"(r1), "=r"(r2), "=r"(r3) : "r"(ad))

#define MMA_FP16(c, a0, a1, a2, a3, b0, b1) \
    asm volatile("mma.sync.aligned.m16n8k16.row.col.f32.f16.f16.f32 " \
        "{%0,%1,%2,%3}, {%4,%5,%6,%7}, {%8,%9}, {%0,%1,%2,%3};" \
        : "+f"((c)[0]), "+f"((c)[1]), "+f"((c)[2]), "+f"((c)[3]) \
        : "r"(a0), "r"(a1), "r"(a2), "r"(a3), "r"(b0), "r"(b1))

// ---------------- fp16 GEMM: R9 config (128x128, 4-stage, 1 sync/chunk) --------
#define ROWB   80
#define A_TILE (128 * ROWB)
#define B_TILE (128 * ROWB)
#define STAGE  (A_TILE + B_TILE)
#define NSTAGE 4
#define GEMM_SMEM (NSTAGE * STAGE + 1024)

__global__ void __launch_bounds__(256)
gemm_fp16_kernel(const __half* __restrict__ A, const __half* __restrict__ Bt,
                 __half* __restrict__ C,
                 const float* __restrict__ a_s, const float* __restrict__ a_d,
                 float* __restrict__ als, float* __restrict__ ald, int K) {
    extern __shared__ char smem[];
    const uint32_t sb = smem_u32(smem);
    float* s_as = (float*)(smem + NSTAGE * STAGE);
    float* s_ad = s_as + 128;

    const int tid = threadIdx.x;
    const int lane = tid & 31;
    const int wid = tid >> 5;
    const int warp_m = wid >> 1;
    const int warp_n = wid & 1;
    const int n0 = blockIdx.x * 128;
    const int m0 = blockIdx.y * 128;
    const int head = n0 >> 8;
    const int nin = n0 & 255;

    if (tid < 128) s_as[tid] = a_s[head * 256 + nin + tid];
    else           s_ad[tid - 128] = a_d[head * 256 + nin + tid - 128];

    const int ld_r = tid >> 2;
    const int ld_c = (tid & 3) << 4;

    const int a_row_l = warp_m * 32 + (lane & 15);
    const int a_colb  = (lane >> 4) << 4;
    const int bg = lane >> 3;
    const int b_row_base = warp_n * 64 + ((bg >> 1) << 3) + (lane & 7);
    const int b_colb  = (bg & 1) << 4;

    float acc[2][8][4];
#pragma unroll
    for (int i = 0; i < 2; ++i)
#pragma unroll
        for (int j = 0; j < 8; ++j)
#pragma unroll
            for (int k = 0; k < 4; ++k) acc[i][j][k] = 0.f;

    const int nch = K >> 5;

#define PREFETCH(CH) do { \
    const int k0 = (CH) << 5; \
    const uint32_t st = sb + ((CH) & (NSTAGE - 1)) * STAGE; \
    _Pragma("unroll") \
    for (int hh = 0; hh < 2; ++hh) { \
        int r = ld_r + hh * 64; \
        CP_ASYNC16(st + r * ROWB + ld_c, A + (size_t)(m0 + r) * K + k0 + (ld_c >> 1)); \
    } \
    _Pragma("unroll") \
    for (int hh = 0; hh < 2; ++hh) { \
        int r = ld_r + hh * 64; \
        CP_ASYNC16(st + A_TILE + r * ROWB + ld_c, Bt + (size_t)(n0 + r) * K + k0 + (ld_c >> 1)); \
    } \
} while (0)

    PREFETCH(0); CP_COMMIT();
    PREFETCH(1); CP_COMMIT();
    PREFETCH(2); CP_COMMIT();

    for (int ch = 0; ch < nch; ++ch) {
        CP_WAIT(2);
        __syncthreads();

        const uint32_t st = sb + (ch & (NSTAGE - 1)) * STAGE;
#pragma unroll
        for (int ks = 0; ks < 2; ++ks) {
            const int kb = ks * 32;
            uint32_t a[2][4], b[4][4];
#pragma unroll
            for (int mt = 0; mt < 2; ++mt) {
                uint32_t ad = st + (a_row_l + mt * 16) * ROWB + kb + a_colb;
                LDMATRIX_X4(a[mt][0], a[mt][1], a[mt][2], a[mt][3], ad);
            }
#pragma unroll
            for (int np = 0; np < 4; ++np) {
                uint32_t ad = st + A_TILE + (b_row_base + np * 16) * ROWB + kb + b_colb;
                LDMATRIX_X4(b[np][0], b[np][1], b[np][2], b[np][3], ad);
            }
#pragma unroll
            for (int mt = 0; mt < 2; ++mt)
#pragma unroll
                for (int np = 0; np < 4; ++np)
#pragma unroll
                    for (int half = 0; half < 2; ++half)
                        MMA_FP16(acc[mt][np * 2 + half],
                                 a[mt][0], a[mt][1], a[mt][2], a[mt][3],
                                 b[np][half * 2], b[np][half * 2 + 1]);
        }
        if (ch + 3 < nch) { PREFETCH(ch + 3); CP_COMMIT(); }
    }

    const int g = lane >> 2;
    const int cpair = (lane & 3) << 1;
#pragma unroll
    for (int mt = 0; mt < 2; ++mt) {
        const int r0g = m0 + warp_m * 32 + mt * 16 + g;
        float ps0 = 0.f, pd0 = 0.f, ps1 = 0.f, pd1 = 0.f;
#pragma unroll
        for (int nt = 0; nt < 8; ++nt) {
            const int colL = warp_n * 64 + nt * 8 + cpair;
            float* c = acc[mt][nt];
            *(__half2*)(C + (size_t)r0g * 512 + n0 + colL) = __floats2half2_rn(c[0], c[1]);
            *(__half2*)(C + (size_t)(r0g + 8) * 512 + n0 + colL) = __floats2half2_rn(c[2], c[3]);
            ps0 += c[0] * s_as[colL] + c[1] * s_as[colL + 1];
            pd0 += c[0] * s_ad[colL] + c[1] * s_ad[colL + 1];
            ps1 += c[2] * s_as[colL] + c[3] * s_as[colL + 1];
            pd1 += c[2] * s_ad[colL] + c[3] * s_ad[colL + 1];
        }
#pragma unroll
        for (int o = 1; o <= 2; o <<= 1) {
            ps0 += __shfl_xor_sync(0xffffffffu, ps0, o);
            pd0 += __shfl_xor_sync(0xffffffffu, pd0, o);
            ps1 += __shfl_xor_sync(0xffffffffu, ps1, o);
            pd1 += __shfl_xor_sync(0xffffffffu, pd1, o);
        }
        if ((lane & 3) == 0) {
            atomicAdd(als + r0g * 2 + head, ps0);
            atomicAdd(ald + r0g * 2 + head, pd0);
            atomicAdd(als + (r0g + 8) * 2 + head, ps1);
            atomicAdd(ald + (r0g + 8) * 2 + head, pd1);
        }
    }
}

// ---------------- conversions ----------------------------------------------------
__global__ void conv_f2h_kernel(const float* __restrict__ in, __half* __restrict__ out, int n4) {
    int i = blockIdx.x * blockDim.x + threadIdx.x;
    if (i >= n4) return;
    float4 v = ((const float4*)in)[i];
    ((__half2*)out)[2 * i + 0] = __floats2half2_rn(v.x, v.y);
    ((__half2*)out)[2 * i + 1] = __floats2half2_rn(v.z, v.w);
}
__global__ void convT_f2h_kernel(const float* __restrict__ W, __half* __restrict__ Wt, int K, int Nn) {
    int o = blockIdx.x * blockDim.x + threadIdx.x;
    if (o >= K * Nn) return;
    int n = o / K, k = o - n * K;
    Wt[o] = __float2half(W[(size_t)k * Nn + n]);
}

// ---------------- direct-bucket CSR -------------------------------------------
__global__ void bucket_fill_kernel(const int* __restrict__ src, const int* __restrict__ dst) {
    int e = blockIdx.x * blockDim.x + threadIdx.x;
    if (e < E_EDGES) {
        int d = dst[e];
        int pos = atomicAdd(&g_deg[d], 1);
        if (pos < BCAP - 1) g_bucket[(size_t)d * BCAP + pos] = src[e];
    }
}

// ---------------- alpha precompute: one warp per dst ----------------------------
// Slots 0..deg-1 = edges (bucket order); slot deg = self loop.
__global__ void __launch_bounds__(256)
compute_alpha_kernel(const float* __restrict__ als, const float* __restrict__ ald) {
    const int w = threadIdx.x >> 5, lane = threadIdx.x & 31;
    const int d = blockIdx.x * 8 + w;
    const int deg = min(g_deg[d], BCAP - 1);
    const int tot = deg + 1;
    const float ad0 = ald[2 * d], ad1 = ald[2 * d + 1];
    const int* bkt = g_bucket + (size_t)d * BCAP;

    // each lane owns slots lane and lane+32 (tot <= 64)
    float e0a = -INFINITY, e1a = -INFINITY, e0b = -INFINITY, e1b = -INFINITY;
    if (lane < tot) {
        int s = (lane < deg) ? bkt[lane] : d;
        e0a = als[2 * s] + ad0;     e0a = e0a > 0.f ? e0a : NEG * e0a;
        e1a = als[2 * s + 1] + ad1; e1a = e1a > 0.f ? e1a : NEG * e1a;
    }
    if (lane + 32 < tot) {
        int s = (lane + 32 < deg) ? bkt[lane + 32] : d;
        e0b = als[2 * s] + ad0;     e0b = e0b > 0.f ? e0b : NEG * e0b;
        e1b = als[2 * s + 1] + ad1; e1b = e1b > 0.f ? e1b : NEG * e1b;
    }
    float m0 = fmaxf(e0a, e0b), m1 = fmaxf(e1a, e1b);
#pragma unroll
    for (int o = 16; o; o >>= 1) {
        m0 = fmaxf(m0, __shfl_xor_sync(0xffffffffu, m0, o));
        m1 = fmaxf(m1, __shfl_xor_sync(0xffffffffu, m1, o));
    }
    float w0a = (lane < tot) ? __expf(e0a - m0) : 0.f;
    float w1a = (lane < tot) ? __expf(e1a - m1) : 0.f;
    float w0b = (lane + 32 < tot) ? __expf(e0b - m0) : 0.f;
    float w1b = (lane + 32 < tot) ? __expf(e1b - m1) : 0.f;
    float q0 = w0a + w0b, q1 = w1a + w1b;
#pragma unroll
    for (int o = 16; o; o >>= 1) {
        q0 += __shfl_xor_sync(0xffffffffu, q0, o);
        q1 += __shfl_xor_sync(0xffffffffu, q1, o);
    }
    const float inv0 = 0.5f / q0, inv1 = 0.5f / q1;  // fold the head-mean 0.5 here
    float2* out = g_alpha + (size_t)d * BCAP;
    if (lane < tot)      out[lane]      = make_float2(w0a * inv0, w1a * inv1);
    if (lane + 32 < tot) out[lane + 32] = make_float2(w0b * inv0, w1b * inv1);
}

// ---------------- smem-staged aggregation ----------------------------------------
// grid = (4 channel-chunks, NUM_AUD). Each CTA stages the audio's h slice
// (800 rows x 64ch x 2 heads fp16 = 200KB) then gathers from smem.
#define AGG_THREADS 512
#define AGG_SMEM (NODES_PER * 256)

__global__ void __launch_bounds__(AGG_THREADS)
gat_aggregate_smem(const __half* __restrict__ h,
                   const float* __restrict__ bias,
                   float* __restrict__ out32, __half* __restrict__ out16,
                   int do_relu) {
    extern __shared__ char smraw[];
    __half* sh = (__half*)smraw;   // [800][128]: [0,64)=head0 chans, [64,128)=head1

    const int chunk = blockIdx.x;        // 0..3
    const int aud   = blockIdx.y;        // 0..63
    const int c0    = chunk * 64;
    const int base  = aud * NODES_PER;
    const int tid   = threadIdx.x;

    // stage: 800 rows x 16 uint4 (seg 0-7 head0, 8-15 head1)
    for (int idx = tid; idx < NODES_PER * 16; idx += AGG_THREADS) {
        const int row = idx >> 4;
        const int seg = idx & 15;
        const int gcol = (seg < 8) ? (c0 + seg * 8) : (256 + c0 + (seg - 8) * 8);
        uint4 v = *(const uint4*)(h + (size_t)(base + row) * 512 + gcol);
        *(uint4*)(sh + row * 128 + seg * 8) = v;
    }
    __syncthreads();

    const int warp = tid >> 5, lane = tid & 31;
    const float b0 = bias[c0 + 2 * lane];
    const float b1 = bias[c0 + 2 * lane + 1];

    for (int dl = warp; dl < NODES_PER; dl += (AGG_THREADS / 32)) {
        const int d = base + dl;
        const int deg = min(g_deg[d], BCAP - 1);
        const int* bkt = g_bucket + (size_t)d * BCAP;
        const float2* alp = g_alpha + (size_t)d * BCAP;

        float a0 = 0.f, a1 = 0.f;   // two output channels per lane
        for (int k = 0; k <= deg; ++k) {
            const int ls = (k < deg) ? (bkt[k] - base) : dl;
            const float2 al = alp[k];
            const __half2 v0 = *(const __half2*)(sh + ls * 128 + 2 * lane);
            const __half2 v1 = *(const __half2*)(sh + ls * 128 + 64 + 2 * lane);
            const float2 f0 = __half22float2(v0);
            const float2 f1 = __half22float2(v1);
            a0 += al.x * f0.x + al.y * f1.x;
            a1 += al.x * f0.y + al.y * f1.y;
        }
        float vx = a0 + b0;          // 0.5 head-mean folded into alpha
        float vy = a1 + b1;
        if (do_relu) { vx = fmaxf(vx, 0.f); vy = fmaxf(vy, 0.f); }
        if (out32) *(float2*)(out32 + (size_t)d * 256 + c0 + 2 * lane) = make_float2(vx, vy);
        if (out16) *(__half2*)(out16 + (size_t)d * 256 + c0 + 2 * lane) = __floats2half2_rn(vx, vy);
    }
}

// ---------------- temporal attention (fp16 emb reads) ---------------------------
__global__ void temporal_attn_kernel(const __half* __restrict__ emb16,
                                     const float* __restrict__ w_att,
                                     const float* __restrict__ b_att,
                                     const float* __restrict__ w_cls,
                                     const float* __restrict__ b_cls,
                                     float* __restrict__ out_audio) {
    const int a = blockIdx.x;
    const int tid = threadIdx.x;
    __shared__ float swa[256];
    __shared__ float slog[NODES_PER];
    __shared__ float sred[256];
    swa[tid] = w_att[tid];
    __syncthreads();
    const int base = a * NODES_PER;
    const int warp = tid >> 5, lane = tid & 31;
    for (int i = warp; i < NODES_PER; i += 8) {
        const __half2* row = (const __half2*)(emb16 + (size_t)(base + i) * 256);
        float p = 0.f;
#pragma unroll
        for (int c = lane; c < 128; c += 32) {
            float2 v = __half22float2(row[c]);
            p += v.x * swa[2 * c] + v.y * swa[2 * c + 1];
        }
#pragma unroll
        for (int o = 16; o; o >>= 1) p += __shfl_xor_sync(0xffffffffu, p, o);
        if (lane == 0) slog[i] = p + b_att[0];
    }
    __syncthreads();
    float m = -INFINITY;
    for (int i = tid; i < NODES_PER; i += 256) m = fmaxf(m, slog[i]);
    sred[tid] = m; __syncthreads();
    for (int o = 128; o; o >>= 1) { if (tid < o) sred[tid] = fmaxf(sred[tid], sred[tid + o]); __syncthreads(); }
    m = sred[0]; __syncthreads();
    float q = 0.f;
    for (int i = tid; i < NODES_PER; i += 256) { float w = expf(slog[i] - m); slog[i] = w; q += w; }
    sred[tid] = q; __syncthreads();
    for (int o = 128; o; o >>= 1) { if (tid < o) sred[tid] += sred[tid + o]; __syncthreads(); }
    float inv = 1.f / sred[0];
    __syncthreads();

    float ac0 = 0.f, ac1 = 0.f, ac2 = 0.f, ac3 = 0.f;
    for (int i = 0; i + 4 <= NODES_PER; i += 4) {
        ac0 += slog[i + 0] * __half2float(emb16[(size_t)(base + i + 0) * 256 + tid]);
        ac1 += slog[i + 1] * __half2float(emb16[(size_t)(base + i + 1) * 256 + tid]);
        ac2 += slog[i + 2] * __half2float(emb16[(size_t)(base + i + 2) * 256 + tid]);
        ac3 += slog[i + 3] * __half2float(emb16[(size_t)(base + i + 3) * 256 + tid]);
    }
    float acc = ((ac0 + ac1) + (ac2 + ac3)) * inv;

    float r0 = acc * w_cls[tid * 2 + 0];
    float r1 = acc * w_cls[tid * 2 + 1];
    sred[tid] = r0; __syncthreads();
    for (int o = 128; o; o >>= 1) { if (tid < o) sred[tid] += sred[tid + o]; __syncthreads(); }
    r0 = sred[0]; __syncthreads();
    sred[tid] = r1; __syncthreads();
    for (int o = 128; o; o >>= 1) { if (tid < o) sred[tid] += sred[tid + o]; __syncthreads(); }
    r1 = sred[0];
    if (tid == 0) {
        out_audio[a * 2 + 0] = r0 + b_cls[0];
        out_audio[a * 2 + 1] = r1 + b_cls[1];
    }
}

// ---------------- launch -------------------------------------------------------
extern "C" void kernel_launch(void* const* d_in, const int* in_sizes, int n_in,
                              void* d_out, int out_size) {
    const float* x     = (const float*)d_in[0];
    const int*   eidx  = (const int*)d_in[1];
    const float* W1    = (const float*)d_in[3];
    const float* a_s1  = (const float*)d_in[4];
    const float* a_d1  = (const float*)d_in[5];
    const float* b1    = (const float*)d_in[6];
    const float* W2    = (const float*)d_in[7];
    const float* a_s2  = (const float*)d_in[8];
    const float* a_d2  = (const float*)d_in[9];
    const float* b2    = (const float*)d_in[10];
    const float* w_att = (const float*)d_in[11];
    const float* b_att = (const float*)d_in[12];
    const float* w_cls = (const float*)d_in[13];
    const float* b_cls = (const float*)d_in[14];

    const int* src = eidx;
    const int* dst = eidx + E_EDGES;

    float* node_emb  = (float*)d_out;
    float* out_audio = (float*)d_out + (size_t)N_NODES * 256;

    void* p;
    cudaGetSymbolAddress(&p, g_h16);   __half* h16   = (__half*)p;
    cudaGetSymbolAddress(&p, g_mh);    __half* mh    = (__half*)p;
    cudaGetSymbolAddress(&p, g_emb16); __half* emb16 = (__half*)p;
    cudaGetSymbolAddress(&p, g_x16);   __half* x16   = (__half*)p;
    cudaGetSymbolAddress(&p, g_w1t);   __half* w1t   = (__half*)p;
    cudaGetSymbolAddress(&p, g_w2t);   __half* w2t   = (__half*)p;
    cudaGetSymbolAddress(&p, g_al);    float*  al    = (float*)p;
    cudaGetSymbolAddress(&p, g_deg);   int*    degp  = (int*)p;
    float* als = al;
    float* ald = al + (size_t)N_NODES * 2;

    cudaFuncSetAttribute(gemm_fp16_kernel, cudaFuncAttributeMaxDynamicSharedMemorySize, GEMM_SMEM);
    cudaFuncSetAttribute(gat_aggregate_smem, cudaFuncAttributeMaxDynamicSharedMemorySize, AGG_SMEM);

    // ---- conversions + direct-bucket CSR ----
    {
        int n4 = N_NODES * 512 / 4;
        conv_f2h_kernel<<<(n4 + 255) / 256, 256>>>(x, x16, n4);
        convT_f2h_kernel<<<(512 * 512 + 255) / 256, 256>>>(W1, w1t, 512, 512);
        convT_f2h_kernel<<<(256 * 512 + 255) / 256, 256>>>(W2, w2t, 256, 512);
    }
    cudaMemsetAsync(degp, 0, N_NODES * sizeof(int));
    bucket_fill_kernel<<<(E_EDGES + 255) / 256, 256>>>(src, dst);

    dim3 agg_grid(4, NUM_AUD);

    // ---- layer 1 ----
    cudaMemsetAsync(al, 0, (size_t)N_NODES * 4 * sizeof(float));
    {
        dim3 grid(4, N_NODES / 128);
        gemm_fp16_kernel<<<grid, 256, GEMM_SMEM>>>(x16, w1t, h16, a_s1, a_d1, als, ald, 512);
    }
    compute_alpha_kernel<<<N_NODES / 8, 256>>>(als, ald);
    gat_aggregate_smem<<<agg_grid, AGG_THREADS, AGG_SMEM>>>(h16, b1, nullptr, mh, 1);

    // ---- layer 2 ----
    cudaMemsetAsync(al, 0, (size_t)N_NODES * 4 * sizeof(float));
    {
        dim3 grid(4, N_NODES / 128);
        gemm_fp16_kernel<<<grid, 256, GEMM_SMEM>>>(mh, w2t, h16, a_s2, a_d2, als, ald, 256);
    }
    compute_alpha_kernel<<<N_NODES / 8, 256>>>(als, ald);
    gat_aggregate_smem<<<agg_grid, AGG_THREADS, AGG_SMEM>>>(h16, b2, node_emb, emb16, 0);

    // ---- temporal attention ----
    temporal_attn_kernel<<<NUM_AUD, 256>>>(emb16, w_att, b_att, w_cls, b_cls, out_audio);
}

// round 13
// speedup vs baseline: 1.4796x; 1.4796x over previous
#include <cuda_runtime.h>
#include <cuda_fp16.h>
#include <math.h>
#include <stdint.h>

#define N_NODES   51200
#define NUM_AUD   64
#define NODES_PER 800
#define E_EDGES   409600
#define NEG       0.2f
#define BCAP      64

// ---------------- scratch ----------------------------------------------------
__device__ __half g_h16[(size_t)N_NODES * 512];
__device__ __half g_mh[(size_t)N_NODES * 256];
__device__ __half g_emb16[(size_t)N_NODES * 256];
__device__ __half g_x16[(size_t)N_NODES * 512];
__device__ __half g_w1t[512 * 512];
__device__ __half g_w2t[512 * 256];
__device__ float  g_al[(size_t)N_NODES * 4];   // als = [0,2N), ald = [2N,4N)
__device__ int    g_deg[N_NODES];
__device__ int    g_bucket[(size_t)N_NODES * BCAP];

// ---------------- PTX helpers --------------------------------------------------
__device__ __forceinline__ uint32_t smem_u32(const void* p) {
    uint32_t a;
    asm("{ .reg .u64 t; cvta.to.shared.u64 t, %1; cvt.u32.u64 %0, t; }" : "=r"(a) : "l"(p));
    return a;
}
#define CP_ASYNC16(sa, ga) asm volatile("cp.async.cg.shared.global [%0], [%1], 16;" :: "r"(sa), "l"(ga))
#define CP_COMMIT()        asm volatile("cp.async.commit_group;" ::: "memory")
#define CP_WAIT(n)         asm volatile("cp.async.wait_group %0;" :: "n"(n) : "memory")

#define LDMATRIX_X4(r0, r1, r2, r3, ad) \
    asm volatile("ldmatrix.sync.aligned.m8n8.x4.shared.b16 {%0,%1,%2,%3}, [%4];" \
        : "=r"(r0), "=r"(r1), "=r"(r2), "=r"(r3) : "r"(ad))

#define MMA_FP16(c, a0, a1, a2, a3, b0, b1) \
    asm volatile("mma.sync.aligned.m16n8k16.row.col.f32.f16.f16.f32 " \
        "{%0,%1,%2,%3}, {%4,%5,%6,%7}, {%8,%9}, {%0,%1,%2,%3};" \
        : "+f"((c)[0]), "+f"((c)[1]), "+f"((c)[2]), "+f"((c)[3]) \
        : "r"(a0), "r"(a1), "r"(a2), "r"(a3), "r"(b0), "r"(b1))

// ---------------- fp16 GEMM: R9 config (128x128, 4-stage, 1 sync/chunk) --------
#define ROWB   80
#define A_TILE (128 * ROWB)
#define B_TILE (128 * ROWB)
#define STAGE  (A_TILE + B_TILE)
#define NSTAGE 4
#define GEMM_SMEM (NSTAGE * STAGE + 1024)

__global__ void __launch_bounds__(256)
gemm_fp16_kernel(const __half* __restrict__ A, const __half* __restrict__ Bt,
                 __half* __restrict__ C,
                 const float* __restrict__ a_s, const float* __restrict__ a_d,
                 float* __restrict__ als, float* __restrict__ ald, int K) {
    extern __shared__ char smem[];
    const uint32_t sb = smem_u32(smem);
    float* s_as = (float*)(smem + NSTAGE * STAGE);
    float* s_ad = s_as + 128;

    const int tid = threadIdx.x;
    const int lane = tid & 31;
    const int wid = tid >> 5;
    const int warp_m = wid >> 1;
    const int warp_n = wid & 1;
    const int n0 = blockIdx.x * 128;
    const int m0 = blockIdx.y * 128;
    const int head = n0 >> 8;
    const int nin = n0 & 255;

    if (tid < 128) s_as[tid] = a_s[head * 256 + nin + tid];
    else           s_ad[tid - 128] = a_d[head * 256 + nin + tid - 128];

    const int ld_r = tid >> 2;
    const int ld_c = (tid & 3) << 4;

    const int a_row_l = warp_m * 32 + (lane & 15);
    const int a_colb  = (lane >> 4) << 4;
    const int bg = lane >> 3;
    const int b_row_base = warp_n * 64 + ((bg >> 1) << 3) + (lane & 7);
    const int b_colb  = (bg & 1) << 4;

    float acc[2][8][4];
#pragma unroll
    for (int i = 0; i < 2; ++i)
#pragma unroll
        for (int j = 0; j < 8; ++j)
#pragma unroll
            for (int k = 0; k < 4; ++k) acc[i][j][k] = 0.f;

    const int nch = K >> 5;

#define PREFETCH(CH) do { \
    const int k0 = (CH) << 5; \
    const uint32_t st = sb + ((CH) & (NSTAGE - 1)) * STAGE; \
    _Pragma("unroll") \
    for (int hh = 0; hh < 2; ++hh) { \
        int r = ld_r + hh * 64; \
        CP_ASYNC16(st + r * ROWB + ld_c, A + (size_t)(m0 + r) * K + k0 + (ld_c >> 1)); \
    } \
    _Pragma("unroll") \
    for (int hh = 0; hh < 2; ++hh) { \
        int r = ld_r + hh * 64; \
        CP_ASYNC16(st + A_TILE + r * ROWB + ld_c, Bt + (size_t)(n0 + r) * K + k0 + (ld_c >> 1)); \
    } \
} while (0)

    PREFETCH(0); CP_COMMIT();
    PREFETCH(1); CP_COMMIT();
    PREFETCH(2); CP_COMMIT();

    for (int ch = 0; ch < nch; ++ch) {
        CP_WAIT(2);
        __syncthreads();

        const uint32_t st = sb + (ch & (NSTAGE - 1)) * STAGE;
#pragma unroll
        for (int ks = 0; ks < 2; ++ks) {
            const int kb = ks * 32;
            uint32_t a[2][4], b[4][4];
#pragma unroll
            for (int mt = 0; mt < 2; ++mt) {
                uint32_t ad = st + (a_row_l + mt * 16) * ROWB + kb + a_colb;
                LDMATRIX_X4(a[mt][0], a[mt][1], a[mt][2], a[mt][3], ad);
            }
#pragma unroll
            for (int np = 0; np < 4; ++np) {
                uint32_t ad = st + A_TILE + (b_row_base + np * 16) * ROWB + kb + b_colb;
                LDMATRIX_X4(b[np][0], b[np][1], b[np][2], b[np][3], ad);
            }
#pragma unroll
            for (int mt = 0; mt < 2; ++mt)
#pragma unroll
                for (int np = 0; np < 4; ++np)
#pragma unroll
                    for (int half = 0; half < 2; ++half)
                        MMA_FP16(acc[mt][np * 2 + half],
                                 a[mt][0], a[mt][1], a[mt][2], a[mt][3],
                                 b[np][half * 2], b[np][half * 2 + 1]);
        }
        if (ch + 3 < nch) { PREFETCH(ch + 3); CP_COMMIT(); }
    }

    const int g = lane >> 2;
    const int cpair = (lane & 3) << 1;
#pragma unroll
    for (int mt = 0; mt < 2; ++mt) {
        const int r0g = m0 + warp_m * 32 + mt * 16 + g;
        float ps0 = 0.f, pd0 = 0.f, ps1 = 0.f, pd1 = 0.f;
#pragma unroll
        for (int nt = 0; nt < 8; ++nt) {
            const int colL = warp_n * 64 + nt * 8 + cpair;
            float* c = acc[mt][nt];
            *(__half2*)(C + (size_t)r0g * 512 + n0 + colL) = __floats2half2_rn(c[0], c[1]);
            *(__half2*)(C + (size_t)(r0g + 8) * 512 + n0 + colL) = __floats2half2_rn(c[2], c[3]);
            ps0 += c[0] * s_as[colL] + c[1] * s_as[colL + 1];
            pd0 += c[0] * s_ad[colL] + c[1] * s_ad[colL + 1];
            ps1 += c[2] * s_as[colL] + c[3] * s_as[colL + 1];
            pd1 += c[2] * s_ad[colL] + c[3] * s_ad[colL + 1];
        }
#pragma unroll
        for (int o = 1; o <= 2; o <<= 1) {
            ps0 += __shfl_xor_sync(0xffffffffu, ps0, o);
            pd0 += __shfl_xor_sync(0xffffffffu, pd0, o);
            ps1 += __shfl_xor_sync(0xffffffffu, ps1, o);
            pd1 += __shfl_xor_sync(0xffffffffu, pd1, o);
        }
        if ((lane & 3) == 0) {
            atomicAdd(als + r0g * 2 + head, ps0);
            atomicAdd(ald + r0g * 2 + head, pd0);
            atomicAdd(als + (r0g + 8) * 2 + head, ps1);
            atomicAdd(ald + (r0g + 8) * 2 + head, pd1);
        }
    }
}

// ---------------- conversions ----------------------------------------------------
__global__ void conv_f2h_kernel(const float* __restrict__ in, __half* __restrict__ out, int n4) {
    int i = blockIdx.x * blockDim.x + threadIdx.x;
    if (i >= n4) return;
    float4 v = ((const float4*)in)[i];
    ((__half2*)out)[2 * i + 0] = __floats2half2_rn(v.x, v.y);
    ((__half2*)out)[2 * i + 1] = __floats2half2_rn(v.z, v.w);
}
__global__ void convT_f2h_kernel(const float* __restrict__ W, __half* __restrict__ Wt, int K, int Nn) {
    int o = blockIdx.x * blockDim.x + threadIdx.x;
    if (o >= K * Nn) return;
    int n = o / K, k = o - n * K;
    Wt[o] = __float2half(W[(size_t)k * Nn + n]);
}

// ---------------- direct-bucket CSR -------------------------------------------
__global__ void bucket_fill_kernel(const int* __restrict__ src, const int* __restrict__ dst) {
    int e = blockIdx.x * blockDim.x + threadIdx.x;
    if (e < E_EDGES) {
        int d = dst[e];
        int pos = atomicAdd(&g_deg[d], 1);
        if (pos < BCAP - 1) g_bucket[(size_t)d * BCAP + pos] = src[e];
    }
}

// ---------------- GAT aggregation: one warp per dst node, 2-way unrolled gather --
__global__ void __launch_bounds__(256)
gat_aggregate_warp(const __half* __restrict__ h,
                   const float* __restrict__ als, const float* __restrict__ ald,
                   const float* __restrict__ bias,
                   float* __restrict__ out32, __half* __restrict__ out16,
                   int do_relu) {
    __shared__ int   s_src[8][BCAP];
    __shared__ float s_a0[8][BCAP], s_a1[8][BCAP];
    const int w = threadIdx.x >> 5, lane = threadIdx.x & 31;
    const int d = blockIdx.x * 8 + w;
    const int deg = min(g_deg[d], BCAP - 1);
    const int tot = deg + 1;
    const float ad0 = ald[2 * d], ad1 = ald[2 * d + 1];
    const int* bkt = g_bucket + (size_t)d * BCAP;

    float m0 = -INFINITY, m1 = -INFINITY;
    for (int k = lane; k < tot; k += 32) {
        int s = (k < deg) ? bkt[k] : d;
        float e0 = als[2 * s] + ad0;     e0 = e0 > 0.f ? e0 : NEG * e0;
        float e1 = als[2 * s + 1] + ad1; e1 = e1 > 0.f ? e1 : NEG * e1;
        s_src[w][k] = s;
        s_a0[w][k] = e0;
        s_a1[w][k] = e1;
        m0 = fmaxf(m0, e0);
        m1 = fmaxf(m1, e1);
    }
#pragma unroll
    for (int o = 16; o; o >>= 1) {
        m0 = fmaxf(m0, __shfl_xor_sync(0xffffffffu, m0, o));
        m1 = fmaxf(m1, __shfl_xor_sync(0xffffffffu, m1, o));
    }
    __syncwarp();
    float q0 = 0.f, q1 = 0.f;
    for (int k = lane; k < tot; k += 32) {
        float w0 = __expf(s_a0[w][k] - m0);
        float w1 = __expf(s_a1[w][k] - m1);
        s_a0[w][k] = w0;
        s_a1[w][k] = w1;
        q0 += w0;
        q1 += w1;
    }
#pragma unroll
    for (int o = 16; o; o >>= 1) {
        q0 += __shfl_xor_sync(0xffffffffu, q0, o);
        q1 += __shfl_xor_sync(0xffffffffu, q1, o);
    }
    const float inv0 = 1.f / q0, inv1 = 1.f / q1;
    __syncwarp();

    float acc0[8] = {}, acc1[8] = {};
    int k = 0;
    // 2-way unrolled: 4 independent uint4 loads in flight per iteration
    for (; k + 2 <= tot; k += 2) {
        const int sA = s_src[w][k];
        const int sB = s_src[w][k + 1];
        const float alA0 = s_a0[w][k] * inv0,     alA1 = s_a1[w][k] * inv1;
        const float alB0 = s_a0[w][k + 1] * inv0, alB1 = s_a1[w][k + 1] * inv1;
        const __half* rowA = h + (size_t)sA * 512;
        const __half* rowB = h + (size_t)sB * 512;
        uint4 uA0 = *(const uint4*)(rowA + 8 * lane);
        uint4 uA1 = *(const uint4*)(rowA + 256 + 8 * lane);
        uint4 uB0 = *(const uint4*)(rowB + 8 * lane);
        uint4 uB1 = *(const uint4*)(rowB + 256 + 8 * lane);
        const __half2* pA0 = (const __half2*)&uA0;
        const __half2* pA1 = (const __half2*)&uA1;
        const __half2* pB0 = (const __half2*)&uB0;
        const __half2* pB1 = (const __half2*)&uB1;
#pragma unroll
        for (int j = 0; j < 4; ++j) {
            float2 vA0 = __half22float2(pA0[j]);
            float2 vA1 = __half22float2(pA1[j]);
            float2 vB0 = __half22float2(pB0[j]);
            float2 vB1 = __half22float2(pB1[j]);
            acc0[2 * j + 0] += alA0 * vA0.x + alB0 * vB0.x;
            acc0[2 * j + 1] += alA0 * vA0.y + alB0 * vB0.y;
            acc1[2 * j + 0] += alA1 * vA1.x + alB1 * vB1.x;
            acc1[2 * j + 1] += alA1 * vA1.y + alB1 * vB1.y;
        }
    }
    for (; k < tot; ++k) {
        const int s = s_src[w][k];
        const float al0 = s_a0[w][k] * inv0;
        const float al1 = s_a1[w][k] * inv1;
        const __half* row = h + (size_t)s * 512;
        uint4 u0 = *(const uint4*)(row + 8 * lane);
        uint4 u1 = *(const uint4*)(row + 256 + 8 * lane);
        const __half2* p0 = (const __half2*)&u0;
        const __half2* p1 = (const __half2*)&u1;
#pragma unroll
        for (int j = 0; j < 4; ++j) {
            float2 v0 = __half22float2(p0[j]);
            float2 v1 = __half22float2(p1[j]);
            acc0[2 * j + 0] += al0 * v0.x;
            acc0[2 * j + 1] += al0 * v0.y;
            acc1[2 * j + 0] += al1 * v1.x;
            acc1[2 * j + 1] += al1 * v1.y;
        }
    }
    const int c0 = 8 * lane;
    float vv[8];
#pragma unroll
    for (int j = 0; j < 8; ++j) {
        float v = 0.5f * (acc0[j] + acc1[j]) + bias[c0 + j];
        if (do_relu) v = fmaxf(v, 0.f);
        vv[j] = v;
    }
    if (out32) {
        *(float4*)(out32 + (size_t)d * 256 + c0) = make_float4(vv[0], vv[1], vv[2], vv[3]);
        *(float4*)(out32 + (size_t)d * 256 + c0 + 4) = make_float4(vv[4], vv[5], vv[6], vv[7]);
    }
    if (out16) {
        __half2 hh[4];
#pragma unroll
        for (int j = 0; j < 4; ++j) hh[j] = __floats2half2_rn(vv[2 * j], vv[2 * j + 1]);
        *(uint4*)(out16 + (size_t)d * 256 + c0) = *(uint4*)hh;
    }
}

// ---------------- temporal attention (fp16 emb reads) ---------------------------
__global__ void temporal_attn_kernel(const __half* __restrict__ emb16,
                                     const float* __restrict__ w_att,
                                     const float* __restrict__ b_att,
                                     const float* __restrict__ w_cls,
                                     const float* __restrict__ b_cls,
                                     float* __restrict__ out_audio) {
    const int a = blockIdx.x;
    const int tid = threadIdx.x;
    __shared__ float swa[256];
    __shared__ float slog[NODES_PER];
    __shared__ float sred[256];
    swa[tid] = w_att[tid];
    __syncthreads();
    const int base = a * NODES_PER;
    const int warp = tid >> 5, lane = tid & 31;
    for (int i = warp; i < NODES_PER; i += 8) {
        const __half2* row = (const __half2*)(emb16 + (size_t)(base + i) * 256);
        float p = 0.f;
#pragma unroll
        for (int c = lane; c < 128; c += 32) {
            float2 v = __half22float2(row[c]);
            p += v.x * swa[2 * c] + v.y * swa[2 * c + 1];
        }
#pragma unroll
        for (int o = 16; o; o >>= 1) p += __shfl_xor_sync(0xffffffffu, p, o);
        if (lane == 0) slog[i] = p + b_att[0];
    }
    __syncthreads();
    float m = -INFINITY;
    for (int i = tid; i < NODES_PER; i += 256) m = fmaxf(m, slog[i]);
    sred[tid] = m; __syncthreads();
    for (int o = 128; o; o >>= 1) { if (tid < o) sred[tid] = fmaxf(sred[tid], sred[tid + o]); __syncthreads(); }
    m = sred[0]; __syncthreads();
    float q = 0.f;
    for (int i = tid; i < NODES_PER; i += 256) { float w = expf(slog[i] - m); slog[i] = w; q += w; }
    sred[tid] = q; __syncthreads();
    for (int o = 128; o; o >>= 1) { if (tid < o) sred[tid] += sred[tid + o]; __syncthreads(); }
    float inv = 1.f / sred[0];
    __syncthreads();

    float ac0 = 0.f, ac1 = 0.f, ac2 = 0.f, ac3 = 0.f;
    for (int i = 0; i + 4 <= NODES_PER; i += 4) {
        ac0 += slog[i + 0] * __half2float(emb16[(size_t)(base + i + 0) * 256 + tid]);
        ac1 += slog[i + 1] * __half2float(emb16[(size_t)(base + i + 1) * 256 + tid]);
        ac2 += slog[i + 2] * __half2float(emb16[(size_t)(base + i + 2) * 256 + tid]);
        ac3 += slog[i + 3] * __half2float(emb16[(size_t)(base + i + 3) * 256 + tid]);
    }
    float acc = ((ac0 + ac1) + (ac2 + ac3)) * inv;

    float r0 = acc * w_cls[tid * 2 + 0];
    float r1 = acc * w_cls[tid * 2 + 1];
    sred[tid] = r0; __syncthreads();
    for (int o = 128; o; o >>= 1) { if (tid < o) sred[tid] += sred[tid + o]; __syncthreads(); }
    r0 = sred[0]; __syncthreads();
    sred[tid] = r1; __syncthreads();
    for (int o = 128; o; o >>= 1) { if (tid < o) sred[tid] += sred[tid + o]; __syncthreads(); }
    r1 = sred[0];
    if (tid == 0) {
        out_audio[a * 2 + 0] = r0 + b_cls[0];
        out_audio[a * 2 + 1] = r1 + b_cls[1];
    }
}

// ---------------- launch -------------------------------------------------------
extern "C" void kernel_launch(void* const* d_in, const int* in_sizes, int n_in,
                              void* d_out, int out_size) {
    const float* x     = (const float*)d_in[0];
    const int*   eidx  = (const int*)d_in[1];
    const float* W1    = (const float*)d_in[3];
    const float* a_s1  = (const float*)d_in[4];
    const float* a_d1  = (const float*)d_in[5];
    const float* b1    = (const float*)d_in[6];
    const float* W2    = (const float*)d_in[7];
    const float* a_s2  = (const float*)d_in[8];
    const float* a_d2  = (const float*)d_in[9];
    const float* b2    = (const float*)d_in[10];
    const float* w_att = (const float*)d_in[11];
    const float* b_att = (const float*)d_in[12];
    const float* w_cls = (const float*)d_in[13];
    const float* b_cls = (const float*)d_in[14];

    const int* src = eidx;
    const int* dst = eidx + E_EDGES;

    float* node_emb  = (float*)d_out;
    float* out_audio = (float*)d_out + (size_t)N_NODES * 256;

    void* p;
    cudaGetSymbolAddress(&p, g_h16);   __half* h16   = (__half*)p;
    cudaGetSymbolAddress(&p, g_mh);    __half* mh    = (__half*)p;
    cudaGetSymbolAddress(&p, g_emb16); __half* emb16 = (__half*)p;
    cudaGetSymbolAddress(&p, g_x16);   __half* x16   = (__half*)p;
    cudaGetSymbolAddress(&p, g_w1t);   __half* w1t   = (__half*)p;
    cudaGetSymbolAddress(&p, g_w2t);   __half* w2t   = (__half*)p;
    cudaGetSymbolAddress(&p, g_al);    float*  al    = (float*)p;
    cudaGetSymbolAddress(&p, g_deg);   int*    degp  = (int*)p;
    float* als = al;
    float* ald = al + (size_t)N_NODES * 2;

    cudaFuncSetAttribute(gemm_fp16_kernel, cudaFuncAttributeMaxDynamicSharedMemorySize, GEMM_SMEM);

    // ---- conversions + direct-bucket CSR ----
    {
        int n4 = N_NODES * 512 / 4;
        conv_f2h_kernel<<<(n4 + 255) / 256, 256>>>(x, x16, n4);
        convT_f2h_kernel<<<(512 * 512 + 255) / 256, 256>>>(W1, w1t, 512, 512);
        convT_f2h_kernel<<<(256 * 512 + 255) / 256, 256>>>(W2, w2t, 256, 512);
    }
    cudaMemsetAsync(degp, 0, N_NODES * sizeof(int));
    bucket_fill_kernel<<<(E_EDGES + 255) / 256, 256>>>(src, dst);

    // ---- layer 1 ----
    cudaMemsetAsync(al, 0, (size_t)N_NODES * 4 * sizeof(float));
    {
        dim3 grid(4, N_NODES / 128);
        gemm_fp16_kernel<<<grid, 256, GEMM_SMEM>>>(x16, w1t, h16, a_s1, a_d1, als, ald, 512);
    }
    gat_aggregate_warp<<<N_NODES / 8, 256>>>(h16, als, ald, b1, nullptr, mh, 1);

    // ---- layer 2 ----
    cudaMemsetAsync(al, 0, (size_t)N_NODES * 4 * sizeof(float));
    {
        dim3 grid(4, N_NODES / 128);
        gemm_fp16_kernel<<<grid, 256, GEMM_SMEM>>>(mh, w2t, h16, a_s2, a_d2, als, ald, 256);
    }
    gat_aggregate_warp<<<N_NODES / 8, 256>>>(h16, als, ald, b2, node_emb, emb16, 0);

    // ---- temporal attention ----
    temporal_attn_kernel<<<NUM_AUD, 256>>>(emb16, w_att, b_att, w_cls, b_cls, out_audio);
}

// round 14
// speedup vs baseline: 1.6511x; 1.1159x over previous
#include <cuda_runtime.h>
#include <cuda_fp16.h>
#include <math.h>
#include <stdint.h>

#define N_NODES   51200
#define NUM_AUD   64
#define NODES_PER 800
#define E_EDGES   409600
#define NEG       0.2f
#define BCAP      64

// ---------------- scratch ----------------------------------------------------
__device__ __half g_h16[(size_t)N_NODES * 512];
__device__ __half g_mh[(size_t)N_NODES * 256];
__device__ __half g_emb16[(size_t)N_NODES * 256];
__device__ __half g_x16[(size_t)N_NODES * 512];
__device__ __half g_w1t[512 * 512];
__device__ __half g_w2t[512 * 256];
__device__ float  g_al[(size_t)N_NODES * 4];   // als = [0,2N), ald = [2N,4N)
__device__ float  g_slog[N_NODES];
__device__ int    g_deg[N_NODES];
__device__ int    g_bucket[(size_t)N_NODES * BCAP];

// ---------------- PTX helpers --------------------------------------------------
__device__ __forceinline__ uint32_t smem_u32(const void* p) {
    uint32_t a;
    asm("{ .reg .u64 t; cvta.to.shared.u64 t, %1; cvt.u32.u64 %0, t; }" : "=r"(a) : "l"(p));
    return a;
}
#define CP_ASYNC16(sa, ga) asm volatile("cp.async.cg.shared.global [%0], [%1], 16;" :: "r"(sa), "l"(ga))
#define CP_COMMIT()        asm volatile("cp.async.commit_group;" ::: "memory")
#define CP_WAIT(n)         asm volatile("cp.async.wait_group %0;" :: "n"(n) : "memory")

#define LDMATRIX_X4(r0, r1, r2, r3, ad) \
    asm volatile("ldmatrix.sync.aligned.m8n8.x4.shared.b16 {%0,%1,%2,%3}, [%4];" \
        : "=r"(r0), "=r"(r1), "=r"(r2), "=r"(r3) : "r"(ad))

#define MMA_FP16(c, a0, a1, a2, a3, b0, b1) \
    asm volatile("mma.sync.aligned.m16n8k16.row.col.f32.f16.f16.f32 " \
        "{%0,%1,%2,%3}, {%4,%5,%6,%7}, {%8,%9}, {%0,%1,%2,%3};" \
        : "+f"((c)[0]), "+f"((c)[1]), "+f"((c)[2]), "+f"((c)[3]) \
        : "r"(a0), "r"(a1), "r"(a2), "r"(a3), "r"(b0), "r"(b1))

// ---------------- fp16 GEMM: R9 config (128x128, 4-stage, 1 sync/chunk) --------
#define ROWB   80
#define A_TILE (128 * ROWB)
#define B_TILE (128 * ROWB)
#define STAGE  (A_TILE + B_TILE)
#define NSTAGE 4
#define GEMM_SMEM (NSTAGE * STAGE + 1024)

__global__ void __launch_bounds__(256)
gemm_fp16_kernel(const __half* __restrict__ A, const __half* __restrict__ Bt,
                 __half* __restrict__ C,
                 const float* __restrict__ a_s, const float* __restrict__ a_d,
                 float* __restrict__ als, float* __restrict__ ald, int K) {
    extern __shared__ char smem[];
    const uint32_t sb = smem_u32(smem);
    float* s_as = (float*)(smem + NSTAGE * STAGE);
    float* s_ad = s_as + 128;

    const int tid = threadIdx.x;
    const int lane = tid & 31;
    const int wid = tid >> 5;
    const int warp_m = wid >> 1;
    const int warp_n = wid & 1;
    const int n0 = blockIdx.x * 128;
    const int m0 = blockIdx.y * 128;
    const int head = n0 >> 8;
    const int nin = n0 & 255;

    if (tid < 128) s_as[tid] = a_s[head * 256 + nin + tid];
    else           s_ad[tid - 128] = a_d[head * 256 + nin + tid - 128];

    const int ld_r = tid >> 2;
    const int ld_c = (tid & 3) << 4;

    const int a_row_l = warp_m * 32 + (lane & 15);
    const int a_colb  = (lane >> 4) << 4;
    const int bg = lane >> 3;
    const int b_row_base = warp_n * 64 + ((bg >> 1) << 3) + (lane & 7);
    const int b_colb  = (bg & 1) << 4;

    float acc[2][8][4];
#pragma unroll
    for (int i = 0; i < 2; ++i)
#pragma unroll
        for (int j = 0; j < 8; ++j)
#pragma unroll
            for (int k = 0; k < 4; ++k) acc[i][j][k] = 0.f;

    const int nch = K >> 5;

#define PREFETCH(CH) do { \
    const int k0 = (CH) << 5; \
    const uint32_t st = sb + ((CH) & (NSTAGE - 1)) * STAGE; \
    _Pragma("unroll") \
    for (int hh = 0; hh < 2; ++hh) { \
        int r = ld_r + hh * 64; \
        CP_ASYNC16(st + r * ROWB + ld_c, A + (size_t)(m0 + r) * K + k0 + (ld_c >> 1)); \
    } \
    _Pragma("unroll") \
    for (int hh = 0; hh < 2; ++hh) { \
        int r = ld_r + hh * 64; \
        CP_ASYNC16(st + A_TILE + r * ROWB + ld_c, Bt + (size_t)(n0 + r) * K + k0 + (ld_c >> 1)); \
    } \
} while (0)

    PREFETCH(0); CP_COMMIT();
    PREFETCH(1); CP_COMMIT();
    PREFETCH(2); CP_COMMIT();

    for (int ch = 0; ch < nch; ++ch) {
        CP_WAIT(2);
        __syncthreads();

        const uint32_t st = sb + (ch & (NSTAGE - 1)) * STAGE;
#pragma unroll
        for (int ks = 0; ks < 2; ++ks) {
            const int kb = ks * 32;
            uint32_t a[2][4], b[4][4];
#pragma unroll
            for (int mt = 0; mt < 2; ++mt) {
                uint32_t ad = st + (a_row_l + mt * 16) * ROWB + kb + a_colb;
                LDMATRIX_X4(a[mt][0], a[mt][1], a[mt][2], a[mt][3], ad);
            }
#pragma unroll
            for (int np = 0; np < 4; ++np) {
                uint32_t ad = st + A_TILE + (b_row_base + np * 16) * ROWB + kb + b_colb;
                LDMATRIX_X4(b[np][0], b[np][1], b[np][2], b[np][3], ad);
            }
#pragma unroll
            for (int mt = 0; mt < 2; ++mt)
#pragma unroll
                for (int np = 0; np < 4; ++np)
#pragma unroll
                    for (int half = 0; half < 2; ++half)
                        MMA_FP16(acc[mt][np * 2 + half],
                                 a[mt][0], a[mt][1], a[mt][2], a[mt][3],
                                 b[np][half * 2], b[np][half * 2 + 1]);
        }
        if (ch + 3 < nch) { PREFETCH(ch + 3); CP_COMMIT(); }
    }

    const int g = lane >> 2;
    const int cpair = (lane & 3) << 1;
#pragma unroll
    for (int mt = 0; mt < 2; ++mt) {
        const int r0g = m0 + warp_m * 32 + mt * 16 + g;
        float ps0 = 0.f, pd0 = 0.f, ps1 = 0.f, pd1 = 0.f;
#pragma unroll
        for (int nt = 0; nt < 8; ++nt) {
            const int colL = warp_n * 64 + nt * 8 + cpair;
            float* c = acc[mt][nt];
            *(__half2*)(C + (size_t)r0g * 512 + n0 + colL) = __floats2half2_rn(c[0], c[1]);
            *(__half2*)(C + (size_t)(r0g + 8) * 512 + n0 + colL) = __floats2half2_rn(c[2], c[3]);
            ps0 += c[0] * s_as[colL] + c[1] * s_as[colL + 1];
            pd0 += c[0] * s_ad[colL] + c[1] * s_ad[colL + 1];
            ps1 += c[2] * s_as[colL] + c[3] * s_as[colL + 1];
            pd1 += c[2] * s_ad[colL] + c[3] * s_ad[colL + 1];
        }
#pragma unroll
        for (int o = 1; o <= 2; o <<= 1) {
            ps0 += __shfl_xor_sync(0xffffffffu, ps0, o);
            pd0 += __shfl_xor_sync(0xffffffffu, pd0, o);
            ps1 += __shfl_xor_sync(0xffffffffu, ps1, o);
            pd1 += __shfl_xor_sync(0xffffffffu, pd1, o);
        }
        if ((lane & 3) == 0) {
            atomicAdd(als + r0g * 2 + head, ps0);
            atomicAdd(ald + r0g * 2 + head, pd0);
            atomicAdd(als + (r0g + 8) * 2 + head, ps1);
            atomicAdd(ald + (r0g + 8) * 2 + head, pd1);
        }
    }
}

// ---------------- fused conversions: x->fp16, W1^T, W2^T -------------------------
#define X4_COUNT (N_NODES * 512 / 4)
#define W1_COUNT (512 * 512)
#define W2_COUNT (256 * 512)

__global__ void convert_all_kernel(const float* __restrict__ x, __half* __restrict__ x16,
                                   const float* __restrict__ W1, __half* __restrict__ w1t,
                                   const float* __restrict__ W2, __half* __restrict__ w2t) {
    int i = blockIdx.x * blockDim.x + threadIdx.x;
    if (i < X4_COUNT) {
        float4 v = ((const float4*)x)[i];
        ((__half2*)x16)[2 * i + 0] = __floats2half2_rn(v.x, v.y);
        ((__half2*)x16)[2 * i + 1] = __floats2half2_rn(v.z, v.w);
        return;
    }
    i -= X4_COUNT;
    if (i < W1_COUNT) {
        int n = i >> 9, k = i & 511;               // K=512, Nn=512
        w1t[i] = __float2half(W1[(size_t)k * 512 + n]);
        return;
    }
    i -= W1_COUNT;
    if (i < W2_COUNT) {
        int n = i >> 8, k = i & 255;               // K=256, Nn=512
        w2t[i] = __float2half(W2[(size_t)k * 512 + n]);
    }
}

// ---------------- direct-bucket CSR -------------------------------------------
__global__ void bucket_fill_kernel(const int* __restrict__ src, const int* __restrict__ dst) {
    int e = blockIdx.x * blockDim.x + threadIdx.x;
    if (e < E_EDGES) {
        int d = dst[e];
        int pos = atomicAdd(&g_deg[d], 1);
        if (pos < BCAP - 1) g_bucket[(size_t)d * BCAP + pos] = src[e];
    }
}

// ---------------- GAT aggregation: one warp per dst node, 2-way unrolled gather --
__global__ void __launch_bounds__(256)
gat_aggregate_warp(const __half* __restrict__ h,
                   const float* __restrict__ als, const float* __restrict__ ald,
                   const float* __restrict__ bias,
                   float* __restrict__ out32, __half* __restrict__ out16,
                   int do_relu) {
    __shared__ int   s_src[8][BCAP];
    __shared__ float s_a0[8][BCAP], s_a1[8][BCAP];
    const int w = threadIdx.x >> 5, lane = threadIdx.x & 31;
    const int d = blockIdx.x * 8 + w;
    const int deg = min(g_deg[d], BCAP - 1);
    const int tot = deg + 1;
    const float ad0 = ald[2 * d], ad1 = ald[2 * d + 1];
    const int* bkt = g_bucket + (size_t)d * BCAP;

    float m0 = -INFINITY, m1 = -INFINITY;
    for (int k = lane; k < tot; k += 32) {
        int s = (k < deg) ? bkt[k] : d;
        float e0 = als[2 * s] + ad0;     e0 = e0 > 0.f ? e0 : NEG * e0;
        float e1 = als[2 * s + 1] + ad1; e1 = e1 > 0.f ? e1 : NEG * e1;
        s_src[w][k] = s;
        s_a0[w][k] = e0;
        s_a1[w][k] = e1;
        m0 = fmaxf(m0, e0);
        m1 = fmaxf(m1, e1);
    }
#pragma unroll
    for (int o = 16; o; o >>= 1) {
        m0 = fmaxf(m0, __shfl_xor_sync(0xffffffffu, m0, o));
        m1 = fmaxf(m1, __shfl_xor_sync(0xffffffffu, m1, o));
    }
    __syncwarp();
    float q0 = 0.f, q1 = 0.f;
    for (int k = lane; k < tot; k += 32) {
        float w0 = __expf(s_a0[w][k] - m0);
        float w1 = __expf(s_a1[w][k] - m1);
        s_a0[w][k] = w0;
        s_a1[w][k] = w1;
        q0 += w0;
        q1 += w1;
    }
#pragma unroll
    for (int o = 16; o; o >>= 1) {
        q0 += __shfl_xor_sync(0xffffffffu, q0, o);
        q1 += __shfl_xor_sync(0xffffffffu, q1, o);
    }
    const float inv0 = 1.f / q0, inv1 = 1.f / q1;
    __syncwarp();
    // normalize once in smem (removes 2 multiplies per row from the gather loop)
    for (int k = lane; k < tot; k += 32) {
        s_a0[w][k] *= inv0;
        s_a1[w][k] *= inv1;
    }
    __syncwarp();

    float acc0[8] = {}, acc1[8] = {};
    int k = 0;
    for (; k + 2 <= tot; k += 2) {
        const int sA = s_src[w][k];
        const int sB = s_src[w][k + 1];
        const float alA0 = s_a0[w][k],     alA1 = s_a1[w][k];
        const float alB0 = s_a0[w][k + 1], alB1 = s_a1[w][k + 1];
        const __half* rowA = h + (size_t)sA * 512;
        const __half* rowB = h + (size_t)sB * 512;
        uint4 uA0 = *(const uint4*)(rowA + 8 * lane);
        uint4 uA1 = *(const uint4*)(rowA + 256 + 8 * lane);
        uint4 uB0 = *(const uint4*)(rowB + 8 * lane);
        uint4 uB1 = *(const uint4*)(rowB + 256 + 8 * lane);
        const __half2* pA0 = (const __half2*)&uA0;
        const __half2* pA1 = (const __half2*)&uA1;
        const __half2* pB0 = (const __half2*)&uB0;
        const __half2* pB1 = (const __half2*)&uB1;
#pragma unroll
        for (int j = 0; j < 4; ++j) {
            float2 vA0 = __half22float2(pA0[j]);
            float2 vA1 = __half22float2(pA1[j]);
            float2 vB0 = __half22float2(pB0[j]);
            float2 vB1 = __half22float2(pB1[j]);
            acc0[2 * j + 0] += alA0 * vA0.x + alB0 * vB0.x;
            acc0[2 * j + 1] += alA0 * vA0.y + alB0 * vB0.y;
            acc1[2 * j + 0] += alA1 * vA1.x + alB1 * vB1.x;
            acc1[2 * j + 1] += alA1 * vA1.y + alB1 * vB1.y;
        }
    }
    for (; k < tot; ++k) {
        const int s = s_src[w][k];
        const float al0 = s_a0[w][k];
        const float al1 = s_a1[w][k];
        const __half* row = h + (size_t)s * 512;
        uint4 u0 = *(const uint4*)(row + 8 * lane);
        uint4 u1 = *(const uint4*)(row + 256 + 8 * lane);
        const __half2* p0 = (const __half2*)&u0;
        const __half2* p1 = (const __half2*)&u1;
#pragma unroll
        for (int j = 0; j < 4; ++j) {
            float2 v0 = __half22float2(p0[j]);
            float2 v1 = __half22float2(p1[j]);
            acc0[2 * j + 0] += al0 * v0.x;
            acc0[2 * j + 1] += al0 * v0.y;
            acc1[2 * j + 0] += al1 * v1.x;
            acc1[2 * j + 1] += al1 * v1.y;
        }
    }
    const int c0 = 8 * lane;
    float vv[8];
#pragma unroll
    for (int j = 0; j < 8; ++j) {
        float v = 0.5f * (acc0[j] + acc1[j]) + bias[c0 + j];
        if (do_relu) v = fmaxf(v, 0.f);
        vv[j] = v;
    }
    if (out32) {
        *(float4*)(out32 + (size_t)d * 256 + c0) = make_float4(vv[0], vv[1], vv[2], vv[3]);
        *(float4*)(out32 + (size_t)d * 256 + c0 + 4) = make_float4(vv[4], vv[5], vv[6], vv[7]);
    }
    if (out16) {
        __half2 hh[4];
#pragma unroll
        for (int j = 0; j < 4; ++j) hh[j] = __floats2half2_rn(vv[2 * j], vv[2 * j + 1]);
        *(uint4*)(out16 + (size_t)d * 256 + c0) = *(uint4*)hh;
    }
}

// ---------------- temporal logits: one warp per node -----------------------------
__global__ void __launch_bounds__(256)
temporal_logits_kernel(const __half* __restrict__ emb16,
                       const float* __restrict__ w_att,
                       const float* __restrict__ b_att,
                       float* __restrict__ slog) {
    const int node = blockIdx.x * 8 + (threadIdx.x >> 5);
    const int lane = threadIdx.x & 31;
    const __half2* row = (const __half2*)(emb16 + (size_t)node * 256);
    float p = 0.f;
#pragma unroll
    for (int c = lane; c < 128; c += 32) {
        float2 v = __half22float2(row[c]);
        p += v.x * w_att[2 * c] + v.y * w_att[2 * c + 1];
    }
#pragma unroll
    for (int o = 16; o; o >>= 1) p += __shfl_xor_sync(0xffffffffu, p, o);
    if (lane == 0) slog[node] = p + b_att[0];
}

// ---------------- temporal attention: softmax + weighted sum --------------------
__global__ void temporal_attn_kernel(const __half* __restrict__ emb16,
                                     const float* __restrict__ slog_g,
                                     const float* __restrict__ w_cls,
                                     const float* __restrict__ b_cls,
                                     float* __restrict__ out_audio) {
    const int a = blockIdx.x;
    const int tid = threadIdx.x;
    __shared__ float slog[NODES_PER];
    __shared__ float sred[256];
    const int base = a * NODES_PER;

    for (int i = tid; i < NODES_PER; i += 256) slog[i] = slog_g[base + i];
    __syncthreads();

    float m = -INFINITY;
    for (int i = tid; i < NODES_PER; i += 256) m = fmaxf(m, slog[i]);
    sred[tid] = m; __syncthreads();
    for (int o = 128; o; o >>= 1) { if (tid < o) sred[tid] = fmaxf(sred[tid], sred[tid + o]); __syncthreads(); }
    m = sred[0]; __syncthreads();
    float q = 0.f;
    for (int i = tid; i < NODES_PER; i += 256) { float w = expf(slog[i] - m); slog[i] = w; q += w; }
    sred[tid] = q; __syncthreads();
    for (int o = 128; o; o >>= 1) { if (tid < o) sred[tid] += sred[tid + o]; __syncthreads(); }
    float inv = 1.f / sred[0];
    __syncthreads();

    float ac0 = 0.f, ac1 = 0.f, ac2 = 0.f, ac3 = 0.f;
    for (int i = 0; i + 4 <= NODES_PER; i += 4) {
        ac0 += slog[i + 0] * __half2float(emb16[(size_t)(base + i + 0) * 256 + tid]);
        ac1 += slog[i + 1] * __half2float(emb16[(size_t)(base + i + 1) * 256 + tid]);
        ac2 += slog[i + 2] * __half2float(emb16[(size_t)(base + i + 2) * 256 + tid]);
        ac3 += slog[i + 3] * __half2float(emb16[(size_t)(base + i + 3) * 256 + tid]);
    }
    float acc = ((ac0 + ac1) + (ac2 + ac3)) * inv;

    float r0 = acc * w_cls[tid * 2 + 0];
    float r1 = acc * w_cls[tid * 2 + 1];
    sred[tid] = r0; __syncthreads();
    for (int o = 128; o; o >>= 1) { if (tid < o) sred[tid] += sred[tid + o]; __syncthreads(); }
    r0 = sred[0]; __syncthreads();
    sred[tid] = r1; __syncthreads();
    for (int o = 128; o; o >>= 1) { if (tid < o) sred[tid] += sred[tid + o]; __syncthreads(); }
    r1 = sred[0];
    if (tid == 0) {
        out_audio[a * 2 + 0] = r0 + b_cls[0];
        out_audio[a * 2 + 1] = r1 + b_cls[1];
    }
}

// ---------------- launch -------------------------------------------------------
extern "C" void kernel_launch(void* const* d_in, const int* in_sizes, int n_in,
                              void* d_out, int out_size) {
    const float* x     = (const float*)d_in[0];
    const int*   eidx  = (const int*)d_in[1];
    const float* W1    = (const float*)d_in[3];
    const float* a_s1  = (const float*)d_in[4];
    const float* a_d1  = (const float*)d_in[5];
    const float* b1    = (const float*)d_in[6];
    const float* W2    = (const float*)d_in[7];
    const float* a_s2  = (const float*)d_in[8];
    const float* a_d2  = (const float*)d_in[9];
    const float* b2    = (const float*)d_in[10];
    const float* w_att = (const float*)d_in[11];
    const float* b_att = (const float*)d_in[12];
    const float* w_cls = (const float*)d_in[13];
    const float* b_cls = (const float*)d_in[14];

    const int* src = eidx;
    const int* dst = eidx + E_EDGES;

    float* node_emb  = (float*)d_out;
    float* out_audio = (float*)d_out + (size_t)N_NODES * 256;

    void* p;
    cudaGetSymbolAddress(&p, g_h16);   __half* h16   = (__half*)p;
    cudaGetSymbolAddress(&p, g_mh);    __half* mh    = (__half*)p;
    cudaGetSymbolAddress(&p, g_emb16); __half* emb16 = (__half*)p;
    cudaGetSymbolAddress(&p, g_x16);   __half* x16   = (__half*)p;
    cudaGetSymbolAddress(&p, g_w1t);   __half* w1t   = (__half*)p;
    cudaGetSymbolAddress(&p, g_w2t);   __half* w2t   = (__half*)p;
    cudaGetSymbolAddress(&p, g_al);    float*  al    = (float*)p;
    cudaGetSymbolAddress(&p, g_slog);  float*  slog  = (float*)p;
    cudaGetSymbolAddress(&p, g_deg);   int*    degp  = (int*)p;
    float* als = al;
    float* ald = al + (size_t)N_NODES * 2;

    cudaFuncSetAttribute(gemm_fp16_kernel, cudaFuncAttributeMaxDynamicSharedMemorySize, GEMM_SMEM);

    // ---- fused conversions + direct-bucket CSR ----
    {
        int total = X4_COUNT + W1_COUNT + W2_COUNT;
        convert_all_kernel<<<(total + 255) / 256, 256>>>(x, x16, W1, w1t, W2, w2t);
    }
    cudaMemsetAsync(degp, 0, N_NODES * sizeof(int));
    bucket_fill_kernel<<<(E_EDGES + 255) / 256, 256>>>(src, dst);

    // ---- layer 1 ----
    cudaMemsetAsync(al, 0, (size_t)N_NODES * 4 * sizeof(float));
    {
        dim3 grid(4, N_NODES / 128);
        gemm_fp16_kernel<<<grid, 256, GEMM_SMEM>>>(x16, w1t, h16, a_s1, a_d1, als, ald, 512);
    }
    gat_aggregate_warp<<<N_NODES / 8, 256>>>(h16, als, ald, b1, nullptr, mh, 1);

    // ---- layer 2 ----
    cudaMemsetAsync(al, 0, (size_t)N_NODES * 4 * sizeof(float));
    {
        dim3 grid(4, N_NODES / 128);
        gemm_fp16_kernel<<<grid, 256, GEMM_SMEM>>>(mh, w2t, h16, a_s2, a_d2, als, ald, 256);
    }
    gat_aggregate_warp<<<N_NODES / 8, 256>>>(h16, als, ald, b2, node_emb, emb16, 0);

    // ---- temporal attention ----
    temporal_logits_kernel<<<N_NODES / 8, 256>>>(emb16, w_att, b_att, slog);
    temporal_attn_kernel<<<NUM_AUD, 256>>>(emb16, slog, w_cls, b_cls, out_audio);
}